// round 2
// baseline (speedup 1.0000x reference)
#include <cuda_runtime.h>
#include <stdint.h>
#include <math.h>

// ---------------------------------------------------------------------------
// InstanceLossBoost pseudo-label update.
//   inputs : c[B,K] f32, pseudo_label_cur[B] i32, index[B] i32   (K=128, B=2M)
//   output : float32 buffer = [ final[B] , index[B] ]  (values cast to float)
//
// final[i] = -1                     if conf[i] <  0.99
//          = cur[i]                 if conf[i] >= 0.99 && cur[i] != -1
//          = pred[i] or -1          if conf[i] >= 0.99 && cur[i] == -1,
//            depending on whether i is within the top-PPC (PPC = ceil(B/K*0.5))
//            most-confident samples of class pred[i] (ties broken by index asc).
//
// Rank only needs the conf>=0.99 subset (anyone ranked above a >=0.99 sample is
// itself >=0.99). Exact selection via 2-level (9+9 bit) radix select over the
// float bit range [bits(0.99f), bits(1.0f)] per class, with exact index
// tie-breaking. Selection kernels early-exit when no class exceeds the quota.
// ---------------------------------------------------------------------------

#define ALPHA_F   0.99f
#define KMAX      256
#define NBINS     512
#define TIE_CAP   16384
#define BCAP      (1 << 22)

__device__ float         g_conf[BCAP];              // 16 MB
__device__ unsigned char g_pred[BCAP];              //  4 MB
__device__ int           g_hist[KMAX];              // high-conf count per class
__device__ int           g_active[KMAX];            // class needs selection
__device__ int           g_needtie[KMAX];
__device__ unsigned int  g_thr[KMAX];               // threshold conf bits
__device__ int           g_radmit[KMAX];            // quota left within tie group
__device__ int           g_sel1[KMAX];              // selected coarse bin
__device__ int           g_rem[KMAX];               // remaining rank to locate
__device__ int           g_h1[KMAX * NBINS];
__device__ int           g_h2[KMAX * NBINS];
__device__ int           g_tiecnt[KMAX];
__device__ int           g_tied[KMAX * TIE_CAP];    // 16 MB
__device__ int           g_nactive;
__device__ int           g_ntie;

// ------------------------------ zero scratch -------------------------------
__global__ void k0_zero() {
    int i = blockIdx.x * blockDim.x + threadIdx.x;
    int stride = gridDim.x * blockDim.x;
    for (int j = i; j < KMAX * NBINS; j += stride) { g_h1[j] = 0; g_h2[j] = 0; }
    for (int j = i; j < KMAX; j += stride) {
        g_hist[j] = 0; g_tiecnt[j] = 0; g_active[j] = 0; g_needtie[j] = 0;
    }
    if (i == 0) { g_nactive = 0; g_ntie = 0; }
}

// ---------------------- main pass: warp-per-row argmax ----------------------
// Block = 256 threads = 8 warps; each block processes chunks of 256 rows.
// Lane l loads float4 at col 4l (512B coalesced per row). Butterfly argmax
// with strictly-greater / min-index tie rule (matches jnp.argmax).
__global__ void k1_main(const float* __restrict__ c,
                        const int*   __restrict__ cur,
                        const int*   __restrict__ idx,
                        float*       __restrict__ out,
                        int B, int writeIdx) {
    __shared__ float s_conf[256];
    __shared__ int   s_pred[256];
    __shared__ int   s_hist[128];

    for (int t = threadIdx.x; t < 128; t += blockDim.x) s_hist[t] = 0;
    __syncthreads();

    const int warp = threadIdx.x >> 5;
    const int lane = threadIdx.x & 31;
    const int nChunks = (B + 255) >> 8;

    for (int chunk = blockIdx.x; chunk < nChunks; chunk += gridDim.x) {
        const int base = chunk << 8;

        // compute phase: warp w handles rows base + w*32 .. base + w*32+31
        for (int t = 0; t < 32; ++t) {
            int r = base + (warp << 5) + t;
            if (r < B) {
                const float4 v =
                    reinterpret_cast<const float4*>(c + (size_t)r * 128)[lane];
                float val = v.x; int vi = lane * 4;
                if (v.y > val) { val = v.y; vi = lane * 4 + 1; }
                if (v.z > val) { val = v.z; vi = lane * 4 + 2; }
                if (v.w > val) { val = v.w; vi = lane * 4 + 3; }
                #pragma unroll
                for (int off = 16; off; off >>= 1) {
                    float ov = __shfl_xor_sync(0xffffffffu, val, off);
                    int   oi = __shfl_xor_sync(0xffffffffu, vi,  off);
                    if (ov > val || (ov == val && oi < vi)) { val = ov; vi = oi; }
                }
                if (lane == 0) {
                    s_conf[(warp << 5) + t] = val;
                    s_pred[(warp << 5) + t] = vi;
                }
            }
        }
        __syncthreads();

        // staging phase: fully coalesced writes + smem histogram
        int i = base + threadIdx.x;
        if (i < B) {
            float cf = s_conf[threadIdx.x];
            int   pv = s_pred[threadIdx.x];
            g_conf[i] = cf;
            g_pred[i] = (unsigned char)pv;
            if (!(cf < ALPHA_F)) atomicAdd(&s_hist[pv], 1);
            int cv = cur[i];
            out[i] = (cf < ALPHA_F) ? -1.0f
                                    : (cv != -1 ? (float)cv : (float)pv);
            if (writeIdx) out[B + i] = (float)idx[i];
        }
        __syncthreads();
    }

    for (int t = threadIdx.x; t < 128; t += blockDim.x) {
        int v = s_hist[t];
        if (v) atomicAdd(&g_hist[t], v);
    }
}

// --------------------- generic fallback (K != 128) --------------------------
__global__ void k1_generic(const float* __restrict__ c,
                           const int*   __restrict__ cur,
                           const int*   __restrict__ idx,
                           float*       __restrict__ out,
                           int B, int K, int writeIdx) {
    int stride = gridDim.x * blockDim.x;
    for (int i = blockIdx.x * blockDim.x + threadIdx.x; i < B; i += stride) {
        const float* row = c + (size_t)i * K;
        float best = row[0]; int bi = 0;
        for (int j = 1; j < K; ++j) {
            float v = row[j];
            if (v > best) { best = v; bi = j; }
        }
        g_conf[i] = best;
        g_pred[i] = (unsigned char)bi;
        if (!(best < ALPHA_F)) atomicAdd(&g_hist[bi], 1);
        int cv = cur[i];
        out[i] = (best < ALPHA_F) ? -1.0f
                                  : (cv != -1 ? (float)cv : (float)bi);
        if (writeIdx) out[B + i] = (float)idx[i];
    }
}

// ------------------------- selection bookkeeping ----------------------------
__global__ void k2_init(int K, int PPC) {
    int k = threadIdx.x;
    if (k >= K) return;
    int act = g_hist[k] > PPC;
    g_active[k] = act;
    g_thr[k]    = 0u;
    g_rem[k]    = PPC;
    g_sel1[k]   = -1;
    g_radmit[k] = 0;
    if (act) atomicAdd(&g_nactive, 1);
}

__global__ void k3_hist1(int B) {
    __shared__ int s_na;
    if (threadIdx.x == 0) s_na = g_nactive;
    __syncthreads();
    if (s_na == 0) return;
    const unsigned LOW = __float_as_uint(ALPHA_F);
    int stride = gridDim.x * blockDim.x;
    for (int i = blockIdx.x * blockDim.x + threadIdx.x; i < B; i += stride) {
        int k = g_pred[i];
        if (!g_active[k]) continue;
        float cf = g_conf[i];
        if (cf < ALPHA_F) continue;
        unsigned rel = __float_as_uint(cf) - LOW;   // <= 0x28F5C (18 bits)
        atomicAdd(&g_h1[k * NBINS + (rel >> 9)], 1);
    }
}

__global__ void k4_res1(int K) {
    int k = threadIdx.x;
    if (k >= K || !g_active[k]) return;
    int rem = g_rem[k], cum = 0;
    for (int b = NBINS - 1; b >= 0; --b) {
        int c = g_h1[k * NBINS + b];
        if (cum + c >= rem) { g_sel1[k] = b; g_rem[k] = rem - cum; break; }
        cum += c;
    }
}

__global__ void k5_hist2(int B) {
    __shared__ int s_na;
    if (threadIdx.x == 0) s_na = g_nactive;
    __syncthreads();
    if (s_na == 0) return;
    const unsigned LOW = __float_as_uint(ALPHA_F);
    int stride = gridDim.x * blockDim.x;
    for (int i = blockIdx.x * blockDim.x + threadIdx.x; i < B; i += stride) {
        int k = g_pred[i];
        if (!g_active[k]) continue;
        float cf = g_conf[i];
        if (cf < ALPHA_F) continue;
        unsigned rel = __float_as_uint(cf) - LOW;
        if ((int)(rel >> 9) != g_sel1[k]) continue;
        atomicAdd(&g_h2[k * NBINS + (rel & (NBINS - 1))], 1);
    }
}

__global__ void k6_res2(int K) {
    int k = threadIdx.x;
    if (k >= K || !g_active[k]) return;
    const unsigned LOW = __float_as_uint(ALPHA_F);
    int rem = g_rem[k], cum = 0;
    for (int b = NBINS - 1; b >= 0; --b) {
        int c = g_h2[k * NBINS + b];
        if (cum + c >= rem) {
            unsigned rel = ((unsigned)g_sel1[k] << 9) | (unsigned)b;
            g_thr[k] = rel + LOW;
            int radmit = rem - cum;          // = quota left within tie group
            g_radmit[k] = radmit;
            if (c > radmit) { g_needtie[k] = 1; atomicAdd(&g_ntie, 1); }
            break;
        }
        cum += c;
    }
}

__global__ void k7_tiecollect(int B) {
    __shared__ int s_nt;
    if (threadIdx.x == 0) s_nt = g_ntie;
    __syncthreads();
    if (s_nt == 0) return;
    int stride = gridDim.x * blockDim.x;
    for (int i = blockIdx.x * blockDim.x + threadIdx.x; i < B; i += stride) {
        int k = g_pred[i];
        if (!g_needtie[k]) continue;
        float cf = g_conf[i];
        if (cf < ALPHA_F) continue;
        if (__float_as_uint(cf) != g_thr[k]) continue;
        int pos = atomicAdd(&g_tiecnt[k], 1);
        if (pos < TIE_CAP) g_tied[k * TIE_CAP + pos] = i;
    }
}

__global__ void k8_final(const int* __restrict__ cur,
                         float* __restrict__ out, int B) {
    __shared__ int s_na;
    if (threadIdx.x == 0) s_na = g_nactive;
    __syncthreads();
    if (s_na == 0) return;
    int stride = gridDim.x * blockDim.x;
    for (int i = blockIdx.x * blockDim.x + threadIdx.x; i < B; i += stride) {
        int k = g_pred[i];
        if (!g_active[k]) continue;
        float cf = g_conf[i];
        if (cf < ALPHA_F) continue;       // out already -1
        if (cur[i] != -1) continue;       // out already cur
        unsigned bits = __float_as_uint(cf);
        unsigned thr  = g_thr[k];
        if (bits > thr) continue;         // admitted, out already pred
        if (bits < thr) { out[i] = -1.0f; continue; }
        // tied exactly at the threshold value
        if (!g_needtie[k]) continue;      // whole tie group admitted
        int cnt = g_tiecnt[k]; if (cnt > TIE_CAP) cnt = TIE_CAP;
        const int* lst = &g_tied[k * TIE_CAP];
        int t = 0;
        for (int j = 0; j < cnt; ++j) t += (lst[j] < i);
        out[i] = (t < g_radmit[k]) ? (float)k : -1.0f;
    }
}

// -----------------------------------------------------------------------------
extern "C" void kernel_launch(void* const* d_in, const int* in_sizes, int n_in,
                              void* d_out, int out_size) {
    const float* c   = (const float*)d_in[0];
    const int*   cur = (const int*)d_in[1];
    const int*   idx = (const int*)d_in[2];
    float*       out = (float*)d_out;

    int B = in_sizes[1];
    int K = (B > 0) ? (int)((long long)in_sizes[0] / B) : 1;
    if (B <= 0 || B > BCAP || K <= 0 || K > KMAX) return;

    int PPC = (int)ceil((double)B / (double)K * 0.5);
    int writeIdx = (out_size >= 2 * B) ? 1 : 0;

    k0_zero<<<256, 256>>>();

    if (K == 128) {
        int nChunks = (B + 255) >> 8;
        int grid = nChunks < 1184 ? nChunks : 1184;
        k1_main<<<grid, 256>>>(c, cur, idx, out, B, writeIdx);
    } else {
        int grid = (B + 255) / 256;
        if (grid > 2048) grid = 2048;
        k1_generic<<<grid, 256>>>(c, cur, idx, out, B, K, writeIdx);
    }

    k2_init<<<1, KMAX>>>(K, PPC);
    k3_hist1<<<256, 256>>>(B);
    k4_res1<<<1, KMAX>>>(K);
    k5_hist2<<<256, 256>>>(B);
    k6_res2<<<1, KMAX>>>(K);
    k7_tiecollect<<<256, 256>>>(B);
    k8_final<<<512, 256>>>(cur, out, B);
}

// round 3
// speedup vs baseline: 1.4370x; 1.4370x over previous
#include <cuda_runtime.h>
#include <stdint.h>
#include <math.h>

// ---------------------------------------------------------------------------
// InstanceLossBoost pseudo-label update.
//   inputs : c[B,K] f32, pseudo_label_cur[B] i32, index[B] i32   (K=128, B=2M)
//   output : float32 buffer = [ final[B] , index[B] ]  (values cast to float)
//
// final[i] = -1                     if conf[i] <  0.99
//          = cur[i]                 if conf[i] >= 0.99 && cur[i] != -1
//          = pred[i] or -1          otherwise, by whether i ranks within the
//            top-PPC (PPC = ceil(B/K*0.5)) most-confident of class pred[i]
//            (ties broken by index asc, matching lexsort stability).
//
// Only the conf>=0.99 subset matters for ranking. Exact 2-level (9+9 bit)
// radix select per class over float bits in [bits(0.99), bits(1.0)], exact
// index tie-breaking. Selection stages early-exit when no class is over quota.
// ---------------------------------------------------------------------------

#define ALPHA_F   0.99f
#define KMAX      256
#define NBINS     512
#define TIE_CAP   16384
#define BCAP      (1 << 22)

__device__ float         g_conf[BCAP];              // 16 MB
__device__ unsigned char g_pred[BCAP];              //  4 MB
__device__ int           g_hist[KMAX];
__device__ int           g_active[KMAX];
__device__ int           g_needtie[KMAX];
__device__ unsigned int  g_thr[KMAX];
__device__ int           g_radmit[KMAX];
__device__ int           g_sel1[KMAX];
__device__ int           g_rem[KMAX];
__device__ int           g_h1[KMAX * NBINS];
__device__ int           g_h2[KMAX * NBINS];
__device__ int           g_tiecnt[KMAX];
__device__ int           g_tied[KMAX * TIE_CAP];    // 16 MB
__device__ int           g_nactive;
__device__ int           g_ntie;
__device__ unsigned int  g_done1;                   // k1 completion counter
__device__ unsigned int  g_doneA;                   // hist1 completion counter
__device__ unsigned int  g_doneB;                   // hist2 completion counter

// ------------------------------ zero scratch -------------------------------
__global__ void k0_zero() {
    int i = blockIdx.x * blockDim.x + threadIdx.x;
    int stride = gridDim.x * blockDim.x;
    for (int j = i; j < KMAX * NBINS; j += stride) { g_h1[j] = 0; g_h2[j] = 0; }
    for (int j = i; j < KMAX; j += stride) {
        g_hist[j] = 0; g_tiecnt[j] = 0; g_active[j] = 0; g_needtie[j] = 0;
    }
    if (i == 0) { g_nactive = 0; g_ntie = 0; g_done1 = 0; g_doneA = 0; g_doneB = 0; }
}

// ------------------ per-class init (shared by fused / generic) --------------
__device__ __forceinline__ void class_init_body(int K, int PPC) {
    // called by one block of >=KMAX threads, block-uniform
    int k = threadIdx.x;
    int act = 0;
    if (k < KMAX) {
        int h = (k < K) ? atomicAdd(&g_hist[k], 0) : 0;
        act = (h > PPC) ? 1 : 0;
        g_active[k] = act;
        g_thr[k]    = 0u;
        g_rem[k]    = PPC;
        g_sel1[k]   = -1;
        g_radmit[k] = 0;
    }
    int na = __syncthreads_count(act);
    if (threadIdx.x == 0) g_nactive = na;
}

// ---------------------- main pass: warp-per-row argmax ----------------------
// Block = 256 threads = 8 warps; chunk = 256 rows. Lane l loads float4 at
// col 4l (512B coalesced/row), 2 rows in flight per warp (MLP=2).
// Argmax = REDUX.max on float bits (non-negative) + ballot + 1 shuffle;
// tie rule = lowest column index (matches jnp.argmax).
__device__ __forceinline__ void argmax_row(const float4 v, float& conf, int& pred) {
    float m  = fmaxf(fmaxf(v.x, v.y), fmaxf(v.z, v.w));
    unsigned wb = __reduce_max_sync(0xffffffffu, __float_as_uint(m));
    float wm = __uint_as_float(wb);
    int local = 4;
    if (v.w == wm) local = 3;
    if (v.z == wm) local = 2;
    if (v.y == wm) local = 1;
    if (v.x == wm) local = 0;
    unsigned mask = __ballot_sync(0xffffffffu, local < 4);
    int src = __ffs(mask) - 1;
    int li  = __shfl_sync(0xffffffffu, local, src);
    conf = wm;
    pred = src * 4 + li;
}

__global__ void k1_main(const float* __restrict__ c,
                        const int*   __restrict__ cur,
                        const int*   __restrict__ idx,
                        float*       __restrict__ out,
                        int B, int writeIdx, int K, int PPC) {
    __shared__ float s_conf[256];
    __shared__ int   s_pred[256];
    __shared__ int   s_hist[128];
    __shared__ int   s_last;

    for (int t = threadIdx.x; t < 128; t += blockDim.x) s_hist[t] = 0;
    __syncthreads();

    const int warp = threadIdx.x >> 5;
    const int lane = threadIdx.x & 31;
    const int nChunks = (B + 255) >> 8;

    for (int chunk = blockIdx.x; chunk < nChunks; chunk += gridDim.x) {
        const int base = chunk << 8;
        const int wbase = base + (warp << 5);

        if (base + 256 <= B) {
            // fast path: full chunk, 2 rows in flight
            #pragma unroll 2
            for (int t = 0; t < 32; t += 2) {
                const float4 a = reinterpret_cast<const float4*>(
                                     c + (size_t)(wbase + t) * 128)[lane];
                const float4 b = reinterpret_cast<const float4*>(
                                     c + (size_t)(wbase + t + 1) * 128)[lane];
                float c0, c1; int p0, p1;
                argmax_row(a, c0, p0);
                argmax_row(b, c1, p1);
                if (lane == 0) {
                    s_conf[(warp << 5) + t]     = c0;
                    s_pred[(warp << 5) + t]     = p0;
                    s_conf[(warp << 5) + t + 1] = c1;
                    s_pred[(warp << 5) + t + 1] = p1;
                }
            }
        } else {
            for (int t = 0; t < 32; ++t) {
                int r = wbase + t;
                if (r < B) {
                    const float4 v = reinterpret_cast<const float4*>(
                                         c + (size_t)r * 128)[lane];
                    float cf; int pv;
                    argmax_row(v, cf, pv);
                    if (lane == 0) {
                        s_conf[(warp << 5) + t] = cf;
                        s_pred[(warp << 5) + t] = pv;
                    }
                }
            }
        }
        __syncthreads();

        int i = base + threadIdx.x;
        if (i < B) {
            float cf = s_conf[threadIdx.x];
            int   pv = s_pred[threadIdx.x];
            g_conf[i] = cf;
            g_pred[i] = (unsigned char)pv;
            if (!(cf < ALPHA_F)) atomicAdd(&s_hist[pv], 1);
            int cv = cur[i];
            out[i] = (cf < ALPHA_F) ? -1.0f
                                    : (cv != -1 ? (float)cv : (float)pv);
            if (writeIdx) out[B + i] = (float)idx[i];
        }
        __syncthreads();
    }

    for (int t = threadIdx.x; t < 128; t += blockDim.x) {
        int v = s_hist[t];
        if (v) atomicAdd(&g_hist[t], v);
    }

    // ---- fused class init: last block to finish does it ----
    __threadfence();
    __syncthreads();
    if (threadIdx.x == 0) {
        unsigned t = atomicAdd(&g_done1, 1);
        s_last = (t == gridDim.x - 1) ? 1 : 0;
    }
    __syncthreads();
    if (s_last) {
        if (threadIdx.x == 0) g_done1 = 0;   // reset for next graph replay
        class_init_body(K, PPC);
    }
}

// --------------------- generic fallback (K != 128) --------------------------
__global__ void k1_generic(const float* __restrict__ c,
                           const int*   __restrict__ cur,
                           const int*   __restrict__ idx,
                           float*       __restrict__ out,
                           int B, int K, int writeIdx) {
    int stride = gridDim.x * blockDim.x;
    for (int i = blockIdx.x * blockDim.x + threadIdx.x; i < B; i += stride) {
        const float* row = c + (size_t)i * K;
        float best = row[0]; int bi = 0;
        for (int j = 1; j < K; ++j) {
            float v = row[j];
            if (v > best) { best = v; bi = j; }
        }
        g_conf[i] = best;
        g_pred[i] = (unsigned char)bi;
        if (!(best < ALPHA_F)) atomicAdd(&g_hist[bi], 1);
        int cv = cur[i];
        out[i] = (best < ALPHA_F) ? -1.0f
                                  : (cv != -1 ? (float)cv : (float)bi);
        if (writeIdx) out[B + i] = (float)idx[i];
    }
}

__global__ void k2_init(int K, int PPC) { class_init_body(K, PPC); }

// -------------------- stage A: coarse histogram + resolve -------------------
__global__ void kA_hist1(int B, int K) {
    __shared__ int s_na, s_last;
    if (threadIdx.x == 0) s_na = g_nactive;
    __syncthreads();
    if (s_na == 0) return;                    // common case: nothing over quota

    const unsigned LOW = __float_as_uint(ALPHA_F);
    int stride = gridDim.x * blockDim.x;
    for (int i = blockIdx.x * blockDim.x + threadIdx.x; i < B; i += stride) {
        int k = g_pred[i];
        if (!g_active[k]) continue;
        float cf = g_conf[i];
        if (cf < ALPHA_F) continue;
        unsigned rel = __float_as_uint(cf) - LOW;   // <= 0x28F5C (18 bits)
        atomicAdd(&g_h1[k * NBINS + (rel >> 9)], 1);
    }

    __threadfence();
    __syncthreads();
    if (threadIdx.x == 0) {
        unsigned t = atomicAdd(&g_doneA, 1);
        s_last = (t == gridDim.x - 1) ? 1 : 0;
    }
    __syncthreads();
    if (s_last) {
        if (threadIdx.x == 0) g_doneA = 0;
        int k = threadIdx.x;
        if (k < K && g_active[k]) {
            int rem = g_rem[k], cum = 0;
            for (int b = NBINS - 1; b >= 0; --b) {
                int cc = atomicAdd(&g_h1[k * NBINS + b], 0);
                if (cum + cc >= rem) { g_sel1[k] = b; g_rem[k] = rem - cum; break; }
                cum += cc;
            }
        }
    }
}

// --------------------- stage B: fine histogram + resolve --------------------
__global__ void kB_hist2(int B, int K) {
    __shared__ int s_na, s_last;
    if (threadIdx.x == 0) s_na = g_nactive;
    __syncthreads();
    if (s_na == 0) return;

    const unsigned LOW = __float_as_uint(ALPHA_F);
    int stride = gridDim.x * blockDim.x;
    for (int i = blockIdx.x * blockDim.x + threadIdx.x; i < B; i += stride) {
        int k = g_pred[i];
        if (!g_active[k]) continue;
        float cf = g_conf[i];
        if (cf < ALPHA_F) continue;
        unsigned rel = __float_as_uint(cf) - LOW;
        if ((int)(rel >> 9) != g_sel1[k]) continue;
        atomicAdd(&g_h2[k * NBINS + (rel & (NBINS - 1))], 1);
    }

    __threadfence();
    __syncthreads();
    if (threadIdx.x == 0) {
        unsigned t = atomicAdd(&g_doneB, 1);
        s_last = (t == gridDim.x - 1) ? 1 : 0;
    }
    __syncthreads();
    if (s_last) {
        if (threadIdx.x == 0) g_doneB = 0;
        int k = threadIdx.x;
        int nt = 0;
        if (k < K && g_active[k]) {
            int rem = g_rem[k], cum = 0;
            for (int b = NBINS - 1; b >= 0; --b) {
                int cc = atomicAdd(&g_h2[k * NBINS + b], 0);
                if (cum + cc >= rem) {
                    unsigned rel = ((unsigned)g_sel1[k] << 9) | (unsigned)b;
                    g_thr[k] = rel + LOW;
                    int radmit = rem - cum;
                    g_radmit[k] = radmit;
                    if (cc > radmit) { g_needtie[k] = 1; nt = 1; }
                    break;
                }
                cum += cc;
            }
        }
        int total = __syncthreads_count(nt);
        if (threadIdx.x == 0) g_ntie = total;
    }
}

__global__ void kC_tiecollect(int B) {
    __shared__ int s_nt;
    if (threadIdx.x == 0) s_nt = g_ntie;
    __syncthreads();
    if (s_nt == 0) return;
    int stride = gridDim.x * blockDim.x;
    for (int i = blockIdx.x * blockDim.x + threadIdx.x; i < B; i += stride) {
        int k = g_pred[i];
        if (!g_needtie[k]) continue;
        float cf = g_conf[i];
        if (cf < ALPHA_F) continue;
        if (__float_as_uint(cf) != g_thr[k]) continue;
        int pos = atomicAdd(&g_tiecnt[k], 1);
        if (pos < TIE_CAP) g_tied[k * TIE_CAP + pos] = i;
    }
}

__global__ void kD_final(const int* __restrict__ cur,
                         float* __restrict__ out, int B) {
    __shared__ int s_na;
    if (threadIdx.x == 0) s_na = g_nactive;
    __syncthreads();
    if (s_na == 0) return;
    int stride = gridDim.x * blockDim.x;
    for (int i = blockIdx.x * blockDim.x + threadIdx.x; i < B; i += stride) {
        int k = g_pred[i];
        if (!g_active[k]) continue;
        float cf = g_conf[i];
        if (cf < ALPHA_F) continue;       // out already -1
        if (cur[i] != -1) continue;       // out already cur
        unsigned bits = __float_as_uint(cf);
        unsigned thr  = g_thr[k];
        if (bits > thr) continue;         // admitted, out already pred
        if (bits < thr) { out[i] = -1.0f; continue; }
        if (!g_needtie[k]) continue;      // whole tie group admitted
        int cnt = g_tiecnt[k]; if (cnt > TIE_CAP) cnt = TIE_CAP;
        const int* lst = &g_tied[k * TIE_CAP];
        int t = 0;
        for (int j = 0; j < cnt; ++j) t += (lst[j] < i);
        out[i] = (t < g_radmit[k]) ? (float)k : -1.0f;
    }
}

// -----------------------------------------------------------------------------
extern "C" void kernel_launch(void* const* d_in, const int* in_sizes, int n_in,
                              void* d_out, int out_size) {
    const float* c   = (const float*)d_in[0];
    const int*   cur = (const int*)d_in[1];
    const int*   idx = (const int*)d_in[2];
    float*       out = (float*)d_out;

    int B = in_sizes[1];
    int K = (B > 0) ? (int)((long long)in_sizes[0] / B) : 1;
    if (B <= 0 || B > BCAP || K <= 0 || K > KMAX) return;

    int PPC = (int)ceil((double)B / (double)K * 0.5);
    int writeIdx = (out_size >= 2 * B) ? 1 : 0;

    k0_zero<<<256, 256>>>();

    if (K == 128) {
        int nChunks = (B + 255) >> 8;
        int grid = nChunks < 1184 ? nChunks : 1184;
        k1_main<<<grid, 256>>>(c, cur, idx, out, B, writeIdx, K, PPC);
    } else {
        int grid = (B + 255) / 256;
        if (grid > 2048) grid = 2048;
        k1_generic<<<grid, 256>>>(c, cur, idx, out, B, K, writeIdx);
        k2_init<<<1, KMAX>>>(K, PPC);
    }

    kA_hist1<<<256, 256>>>(B, K);
    kB_hist2<<<256, 256>>>(B, K);
    kC_tiecollect<<<256, 256>>>(B);
    kD_final<<<512, 256>>>(cur, out, B);
}